// round 14
// baseline (speedup 1.0000x reference)
#include <cuda_runtime.h>
#include <cuda_fp16.h>
#include <stdint.h>

// MX fp8 (e4m3) fake quantization, block=32, shared e8m0 exponent.
//
// Both-ends TMA bulk version: each 256-thread CTA owns a 16KB tile.
//   1. ONE cp.async.bulk global->shared (UBLKCP) pulls the 16KB input tile
//      into SMEM (single contiguous DRAM read burst per CTA).
//   2. Threads LDS their 8+8 floats, fake-quantize (packed-exponent 4-lane
//      shfl reduction + HW e4m3 converter), write results back IN PLACE.
//   3. ONE cp.async.bulk shared->global (UTMASTG) writes the 16KB tile out
//      (single contiguous DRAM write burst per CTA — measured +1.5% in R12).
// Large per-CTA bursts on both directions minimize DRAM R/W turnaround.
// 8 CTAs/SM cover the TMA-in latency exactly as they covered LDG latency.
//
// Block amax matters only via its fp32 exponent field (exp-field max ==
// exp field of amax for nonneg floats). e-field==0 (zero/subnormal amax)
// maps to sexp=-127, matching the reference's TINY/clip path.
//
// Element quantization uses the HW e4m3 converter:
//   cvt.rn.satfinite.e4m3x2.f32 == round-half-even onto the e4m3 grid
//   (subnormal step 2^-9, saturate to +-448)
// bit-identical to the reference's priv_exp/pscale/round/clip chain; decode
// is exact via cvt.rn.f16x2.e4m3x2 + f16->f32.

static __device__ __forceinline__ float2 qdq_pair(float x, float y,
                                                  float inv, float scale) {
    float xs = x * inv;                       // exact (power-of-2 scale)
    float ys = y * inv;
    unsigned short p8;
    asm("cvt.rn.satfinite.e4m3x2.f32 %0, %1, %2;"
        : "=h"(p8) : "f"(ys), "f"(xs));       // x -> lo byte
    unsigned h2;
    asm("cvt.rn.f16x2.e4m3x2 %0, %1;" : "=r"(h2) : "h"(p8));
    __half2 hh = *reinterpret_cast<__half2*>(&h2);   // lo=x, hi=y (exact)
    float2 f = __half22float2(hh);
    f.x *= scale;
    f.y *= scale;
    return f;
}

static __device__ __forceinline__ float amax8(const float4& a,
                                              const float4& b) {
    float m0 = fmaxf(fmaxf(fabsf(a.x), fabsf(a.y)), fmaxf(fabsf(a.z), fabsf(a.w)));
    float m1 = fmaxf(fmaxf(fabsf(b.x), fabsf(b.y)), fmaxf(fabsf(b.z), fabsf(b.w)));
    return fmaxf(m0, m1);
}

__global__ void __launch_bounds__(256) mx_fp8_fq_kernel(
    const float* __restrict__ in, float* __restrict__ out) {
    __shared__ __align__(128) float tile[4096];   // 16KB in-place tile
    __shared__ __align__(8) unsigned long long mbar;

    int tid = threadIdx.x;
    int warp = tid >> 5;
    int lane = tid & 31;
    int local = warp * 512 + lane * 8;            // float offset inside tile
    int cta_base = blockIdx.x * 4096;             // fits 32-bit (n = 2^26)

    unsigned mb = (unsigned)__cvta_generic_to_shared(&mbar);
    unsigned sti = (unsigned)__cvta_generic_to_shared(tile);

    if (tid == 0) {
        asm volatile("mbarrier.init.shared.b64 [%0], 1;" :: "r"(mb) : "memory");
    }
    __syncthreads();

    if (tid == 0) {
        asm volatile("mbarrier.arrive.expect_tx.shared.b64 _, [%0], %1;"
                     :: "r"(mb), "r"(16384u) : "memory");
        asm volatile(
            "cp.async.bulk.shared::cta.global.mbarrier::complete_tx::bytes "
            "[%0], [%1], %2, [%3];"
            :: "r"(sti), "l"(in + cta_base), "r"(16384u), "r"(mb) : "memory");
    }

    // Wait for the input tile (parity 0, acquire).
    {
        unsigned done;
        asm volatile(
            "{\n\t.reg .pred p;\n\t"
            "mbarrier.try_wait.parity.acquire.cta.shared::cta.b64 p, [%1], 0;\n\t"
            "selp.b32 %0, 1, 0, p;\n\t}"
            : "=r"(done) : "r"(mb) : "memory");
        if (!done) {
            asm volatile(
                "{\n\t.reg .pred P1;\n\t"
                "WAIT_LOOP_%=:\n\t"
                "mbarrier.try_wait.parity.acquire.cta.shared::cta.b64 P1, [%0], 0, 0x989680;\n\t"
                "@P1 bra.uni WAIT_DONE_%=;\n\t"
                "bra.uni WAIT_LOOP_%=;\n\t"
                "WAIT_DONE_%=:\n\t}"
                :: "r"(mb) : "memory");
        }
    }

    // Load this thread's 16 floats from SMEM.
    const float4* tp = reinterpret_cast<const float4*>(tile);
    float4 a0 = tp[(local >> 2)];
    float4 a1 = tp[(local >> 2) + 1];
    float4 b0 = tp[(local + 256) >> 2];
    float4 b1 = tp[((local + 256) >> 2) + 1];

    // Per-group amax -> exponent byte; group A in byte 0, group B in byte 1.
    unsigned packed = (__float_as_uint(amax8(a0, a1)) >> 23)
                    | ((__float_as_uint(amax8(b0, b1)) >> 23) << 8);

    // 4-lane segmented reduction (each 8-float group sits inside one block).
    packed = __vmaxu4(packed, __shfl_xor_sync(0xffffffffu, packed, 1));
    packed = __vmaxu4(packed, __shfl_xor_sync(0xffffffffu, packed, 2));

    float4* tw = reinterpret_cast<float4*>(tile);
#pragma unroll
    for (int j = 0; j < 2; j++) {
        int e = (packed >> (8 * j)) & 0xff;
        int sexp = max(e - 135, -127);   // floor(log2(amax)) - 8, clipped low
        // scale = 2^sexp (sexp==-127 -> subnormal 0x00400000); inv = 2^-sexp.
        float scale = __int_as_float(max((sexp + 127) << 23, 0x00400000));
        float inv   = __int_as_float((127 - sexp) << 23);
        const float4& va = (j == 0) ? a0 : b0;
        const float4& vb = (j == 0) ? a1 : b1;
        float2 p0 = qdq_pair(va.x, va.y, inv, scale);
        float2 p1 = qdq_pair(va.z, va.w, inv, scale);
        float2 p2 = qdq_pair(vb.x, vb.y, inv, scale);
        float2 p3 = qdq_pair(vb.z, vb.w, inv, scale);
        int o = (local + 256 * j) >> 2;
        tw[o]     = make_float4(p0.x, p0.y, p1.x, p1.y);
        tw[o + 1] = make_float4(p2.x, p2.y, p3.x, p3.y);
    }

    __syncthreads();

    // One 16KB contiguous bulk store per CTA (UTMASTG path).
    if (tid == 0) {
        asm volatile("fence.proxy.async.shared::cta;" ::: "memory");
        asm volatile(
            "cp.async.bulk.global.shared::cta.bulk_group [%0], [%1], %2;"
            :: "l"(out + cta_base), "r"(sti), "r"(16384u) : "memory");
        asm volatile("cp.async.bulk.commit_group;" ::: "memory");
        asm volatile("cp.async.bulk.wait_group 0;" ::: "memory");
    }
}

extern "C" void kernel_launch(void* const* d_in, const int* in_sizes, int n_in,
                              void* d_out, int out_size) {
    const float* in = (const float*)d_in[0];
    float* out = (float*)d_out;
    int n = in_sizes[0];              // 8192*8192
    int blocks = n / 4096;            // 16384 CTAs, one 16KB tile each
    mx_fp8_fq_kernel<<<blocks, 256>>>(in, out);
}

// round 15
// speedup vs baseline: 1.0066x; 1.0066x over previous
#include <cuda_runtime.h>
#include <cuda_fp16.h>
#include <stdint.h>

// MX fp8 (e4m3) fake quantization, block=32, shared e8m0 exponent.
//
// R12 champion config (LDG.256 reads + TMA bulk-store epilogue) with a
// split-store refinement: the 16KB staging tile is written out as TWO 8KB
// UTMASTG bursts, each launched as soon as ITS half-CTA (4 warps, named
// barrier) finishes compute. The write burst starts before the slowest warp
// of the other half is done, shortening the per-CTA critical path while
// keeping large contiguous write bursts (8KB >> the 1KB LSU fragments that
// the R12 experiment showed were the problem).
//
// Block amax matters only via its fp32 exponent field (exp-field max ==
// exp field of amax for nonneg floats). e-field==0 (zero/subnormal amax)
// maps to sexp=-127, matching the reference's TINY/clip path.
//
// Element quantization uses the HW e4m3 converter:
//   cvt.rn.satfinite.e4m3x2.f32 == round-half-even onto the e4m3 grid
//   (subnormal step 2^-9, saturate to +-448)
// bit-identical to the reference's priv_exp/pscale/round/clip chain; decode
// is exact via cvt.rn.f16x2.e4m3x2 + f16->f32.

static __device__ __forceinline__ float2 qdq_pair(float x, float y,
                                                  float inv, float scale) {
    float xs = x * inv;                       // exact (power-of-2 scale)
    float ys = y * inv;
    unsigned short p8;
    asm("cvt.rn.satfinite.e4m3x2.f32 %0, %1, %2;"
        : "=h"(p8) : "f"(ys), "f"(xs));       // x -> lo byte
    unsigned h2;
    asm("cvt.rn.f16x2.e4m3x2 %0, %1;" : "=r"(h2) : "h"(p8));
    __half2 hh = *reinterpret_cast<__half2*>(&h2);   // lo=x, hi=y (exact)
    float2 f = __half22float2(hh);
    f.x *= scale;
    f.y *= scale;
    return f;
}

static __device__ __forceinline__ void ldg256_stream(const float* p, float4& a,
                                                     float4& b) {
    asm("ld.global.cs.L2::256B.v8.f32 {%0,%1,%2,%3,%4,%5,%6,%7}, [%8];"
        : "=f"(a.x), "=f"(a.y), "=f"(a.z), "=f"(a.w),
          "=f"(b.x), "=f"(b.y), "=f"(b.z), "=f"(b.w)
        : "l"(p));
}

static __device__ __forceinline__ float amax8(const float4& a,
                                              const float4& b) {
    float m0 = fmaxf(fmaxf(fabsf(a.x), fabsf(a.y)), fmaxf(fabsf(a.z), fabsf(a.w)));
    float m1 = fmaxf(fmaxf(fabsf(b.x), fabsf(b.y)), fmaxf(fabsf(b.z), fabsf(b.w)));
    return fmaxf(m0, m1);
}

static __device__ __forceinline__ void bulk_store(float* dst, unsigned saddr,
                                                  unsigned bytes) {
    asm volatile("fence.proxy.async.shared::cta;" ::: "memory");
    asm volatile(
        "cp.async.bulk.global.shared::cta.bulk_group [%0], [%1], %2;"
        :: "l"(dst), "r"(saddr), "r"(bytes) : "memory");
    asm volatile("cp.async.bulk.commit_group;" ::: "memory");
    asm volatile("cp.async.bulk.wait_group 0;" ::: "memory");
}

__global__ void __launch_bounds__(256) mx_fp8_fq_kernel(
    const float* __restrict__ in, float* __restrict__ out) {
    __shared__ __align__(128) float tile[4096];   // 16KB staging, two halves

    int tid = threadIdx.x;
    int warp = tid >> 5;
    int lane = tid & 31;
    int local = warp * 512 + lane * 8;            // float offset inside tile
    int cta_base = blockIdx.x * 4096;             // fits 32-bit (n = 2^26)
    const float* pin = in + cta_base + local;

    // Two front-batched 256-bit loads per thread (64B in flight).
    float4 a0, a1, b0, b1;
    ldg256_stream(pin, a0, a1);
    ldg256_stream(pin + 256, b0, b1);

    // Per-load amax -> exponent byte; load A in byte 0, load B in byte 1.
    unsigned packed = (__float_as_uint(amax8(a0, a1)) >> 23)
                    | ((__float_as_uint(amax8(b0, b1)) >> 23) << 8);

    // 4-lane segmented reduction (each v8 load sits inside one quant block).
    packed = __vmaxu4(packed, __shfl_xor_sync(0xffffffffu, packed, 1));
    packed = __vmaxu4(packed, __shfl_xor_sync(0xffffffffu, packed, 2));

#pragma unroll
    for (int j = 0; j < 2; j++) {
        int e = (packed >> (8 * j)) & 0xff;
        int sexp = max(e - 135, -127);   // floor(log2(amax)) - 8, clipped low
        // scale = 2^sexp (sexp==-127 -> subnormal 0x00400000); inv = 2^-sexp.
        float scale = __int_as_float(max((sexp + 127) << 23, 0x00400000));
        float inv   = __int_as_float((127 - sexp) << 23);
        const float4& va = (j == 0) ? a0 : b0;
        const float4& vb = (j == 0) ? a1 : b1;
        float2 p0 = qdq_pair(va.x, va.y, inv, scale);
        float2 p1 = qdq_pair(va.z, va.w, inv, scale);
        float2 p2 = qdq_pair(vb.x, vb.y, inv, scale);
        float2 p3 = qdq_pair(vb.z, vb.w, inv, scale);
        float4* ts = reinterpret_cast<float4*>(&tile[local + 256 * j]);
        ts[0] = make_float4(p0.x, p0.y, p1.x, p1.y);
        ts[1] = make_float4(p2.x, p2.y, p3.x, p3.y);
    }

    // Split epilogue: each half-CTA (4 warps = first/second 8KB of the tile)
    // syncs on its own named barrier and launches its 8KB burst immediately.
    if (warp < 4) {
        asm volatile("bar.sync 1, 128;" ::: "memory");
        if (tid == 0) {
            unsigned saddr = (unsigned)__cvta_generic_to_shared(tile);
            bulk_store(out + cta_base, saddr, 8192u);
        }
    } else {
        asm volatile("bar.sync 2, 128;" ::: "memory");
        if (tid == 128) {
            unsigned saddr = (unsigned)__cvta_generic_to_shared(tile + 2048);
            bulk_store(out + cta_base + 2048, saddr, 8192u);
        }
    }
}

extern "C" void kernel_launch(void* const* d_in, const int* in_sizes, int n_in,
                              void* d_out, int out_size) {
    const float* in = (const float*)d_in[0];
    float* out = (float*)d_out;
    int n = in_sizes[0];              // 8192*8192
    int blocks = n / 4096;            // 16384 CTAs, one 16KB tile each
    mx_fp8_fq_kernel<<<blocks, 256>>>(in, out);
}